// round 14
// baseline (speedup 1.0000x reference)
#include <cuda_runtime.h>
#include <cuda_bf16.h>
#include <math.h>
#include <stdint.h>

#define BATCH 4
#define SEQ   2048
#define EMB   1024
#define HID   1024
#define MTOT  (BATCH * SEQ)

// ---------------------------------------------------------------------------
// Device-global scratch
// ---------------------------------------------------------------------------
__device__ __nv_bfloat16 g_xh[MTOT * EMB], g_xl[MTOT * EMB];
__device__ __nv_bfloat16 g_wvh[HID * EMB], g_wvl[HID * EMB];
__device__ __nv_bfloat16 g_wqth[EMB * HID], g_wqtl[EMB * HID];  // Wq^T
__device__ __nv_bfloat16 g_wkth[EMB * HID], g_wktl[EMB * HID];  // Wk^T
__device__ float         g_mp[8 * 1024 * 1024];                 // Mt split-K partials
__device__ __nv_bfloat16 g_mth[EMB * EMB], g_mtl[EMB * EMB];    // Mt = (WqT Wk)^T layout
__device__ __nv_bfloat16 g_th[MTOT * EMB], g_tl[MTOT * EMB];    // t = x M
__device__ __nv_bfloat16 g_vth[BATCH * HID * SEQ], g_vtl[BATCH * HID * SEQ];
__device__ float         g_s [(size_t)BATCH * SEQ * SEQ];
__device__ __nv_bfloat16 g_ah[(size_t)BATCH * SEQ * SEQ];
__device__ __nv_bfloat16 g_al[(size_t)BATCH * SEQ * SEQ];
__device__ float         g_inv[MTOT];
__device__ float         g_r1[EMB], g_r2[EMB], g_c[1];
__device__ float         g_u[MTOT], g_w[MTOT];

// ---------------------------------------------------------------------------
// Helpers
// ---------------------------------------------------------------------------
__device__ __forceinline__ uint32_t smem_u32(const void* p) {
    uint32_t a;
    asm("{ .reg .u64 t; cvta.to.shared.u64 t, %1; cvt.u32.u64 %0, t; }"
        : "=r"(a) : "l"(p));
    return a;
}

__device__ __forceinline__ uint32_t pack2(__nv_bfloat16 a, __nv_bfloat16 b) {
    __nv_bfloat162 t = __halves2bfloat162(a, b);
    return *reinterpret_cast<uint32_t*>(&t);
}

__device__ __forceinline__ void split1(float v, __nv_bfloat16& h, __nv_bfloat16& l) {
    h = __float2bfloat16_rn(v);
    l = __float2bfloat16_rn(v - __bfloat162float(h));
}

// FMA-pipe exp (degree-6 2^f poly, rel err ~1.2e-7)
__device__ __forceinline__ float fexp(float x) {
    x = fminf(fmaxf(x, -87.f), 87.f);
    const float t = x * 1.4426950408889634f;
    const int i = __float2int_rn(t);
    const float f = t - (float)i;
    float p = 1.54035304e-4f;
    p = fmaf(p, f, 1.33335581e-3f);
    p = fmaf(p, f, 9.61812910e-3f);
    p = fmaf(p, f, 5.55041086e-2f);
    p = fmaf(p, f, 2.40226462e-1f);
    p = fmaf(p, f, 6.93147182e-1f);
    p = fmaf(p, f, 1.0f);
    return p * __int_as_float((i + 127) << 23);
}

#define CP16(dst, src)                                                         \
    asm volatile("cp.async.cg.shared.global [%0], [%1], 16;" ::"r"(dst),       \
                 "l"(src))
#define CP_COMMIT() asm volatile("cp.async.commit_group;" ::: "memory")
#define CP_WAIT1()  asm volatile("cp.async.wait_group 1;" ::: "memory")

__device__ __forceinline__ void ldsm4(uint32_t* r, uint32_t addr) {
    asm volatile(
        "ldmatrix.sync.aligned.m8n8.x4.shared.b16 {%0,%1,%2,%3}, [%4];"
        : "=r"(r[0]), "=r"(r[1]), "=r"(r[2]), "=r"(r[3])
        : "r"(addr));
}

__device__ __forceinline__ void mma_bf16(float* c, const uint32_t* a,
                                         uint32_t b0, uint32_t b1) {
    asm volatile(
        "mma.sync.aligned.m16n8k16.row.col.f32.bf16.bf16.f32 "
        "{%0,%1,%2,%3}, {%4,%5,%6,%7}, {%8,%9}, {%0,%1,%2,%3};"
        : "+f"(c[0]), "+f"(c[1]), "+f"(c[2]), "+f"(c[3])
        : "r"(a[0]), "r"(a[1]), "r"(a[2]), "r"(a[3]), "r"(b0), "r"(b1));
}

__device__ __forceinline__ uint32_t swz(int row, int unit) {
    return (uint32_t)(row * 64 + ((unit ^ ((row >> 1) & 3)) << 4));
}

// ---------------------------------------------------------------------------
// bf16x3 emulated-fp32 GEMM via mma.sync (NT): D[m,n] = sum_k A[m,k]*B[n,k]
// (mainloop = proven R11 form; per-batch launches pass pre-offset pointers)
// MODE 0: plain bf16 hi/lo out                        (t = x·M, per batch)
// MODE 5: V projection (+bias), transpose epilogue -> [b][h][s] bf16 hi/lo
// MODE 6: Mt split-K partials (bz = K-part, fp32 partial out)
// MODE 2: scores = t·x^T + u[q] + w[k], *scale, fp32 out, triangular (1 batch)
// MODE 3: attn @ V^T; per-row inv[] norm, K truncated causally (1 batch)
// ---------------------------------------------------------------------------
#define BKC 32
#define STAGES 3
#define STAGE_BYTES (4 * 128 * BKC * 2)
#define GEMM_SMEM (STAGES * STAGE_BYTES)
#define OFF_AH 0
#define OFF_AL (128 * BKC * 2)
#define OFF_BH (2 * 128 * BKC * 2)
#define OFF_BL (3 * 128 * BKC * 2)

#define N_TRI 136   // 16*17/2 score tiles per batch

template <int MODE>
__global__ __launch_bounds__(256, 2)
void gemm_tc(const __nv_bfloat16* __restrict__ Ah, const __nv_bfloat16* __restrict__ Al,
             const __nv_bfloat16* __restrict__ Bh, const __nv_bfloat16* __restrict__ Bl,
             const float* __restrict__ bias_v,
             float* __restrict__ Cf,
             __nv_bfloat16* __restrict__ Chi, __nv_bfloat16* __restrict__ Clo,
             __nv_bfloat16* __restrict__ Vth, __nv_bfloat16* __restrict__ Vtl,
             const float* __restrict__ uvec, const float* __restrict__ wvec,
             const float* __restrict__ invp,
             int K, int lda, int ldb, int ldc, float scale) {
    int bm, bn, bz = 0;
    int koff = 0;
    if (MODE == 2) {
        const int t0 = blockIdx.x;
        int t = (int)((sqrtf(8.f * t0 + 1.f) - 1.f) * 0.5f);
        while ((t + 1) * (t + 2) / 2 <= t0) t++;
        while (t * (t + 1) / 2 > t0) t--;
        bm = t;
        bn = t0 - t * (t + 1) / 2;
    } else if (MODE == 3) {
        bn = blockIdx.x;
        bm = gridDim.y - 1 - blockIdx.y;  // heavy rows first
    } else if (MODE == 6) {
        bn = blockIdx.x;
        bm = blockIdx.y;
        bz = blockIdx.z;        // K-part
        koff = bz * 128;        // 4 chunks of 32
    } else {                    // MODE 0 / 5
        bn = blockIdx.x;
        bm = blockIdx.y;
    }

    extern __shared__ __align__(1024) char smem[];
    const uint32_t sb = smem_u32(smem);

    const int tid = threadIdx.x;
    const int wid = tid >> 5, lane = tid & 31;

    const __nv_bfloat16* pAh = Ah + (size_t)bm * 128 * lda;
    const __nv_bfloat16* pAl = Al + (size_t)bm * 128 * lda;
    const __nv_bfloat16* pBh = Bh + (size_t)bn * 128 * ldb;
    const __nv_bfloat16* pBl = Bl + (size_t)bn * 128 * ldb;

    int nch = K / BKC;
    if (MODE == 3) nch = 4 * (bm + 1);
    if (MODE == 6) nch = 4;

    const int fr0 = tid >> 2, fu0 = tid & 3;
    const int fr1 = (tid + 256) >> 2, fu1 = tid & 3;

    auto fill = [&](int stage, int ck) {
        const uint32_t base = sb + stage * STAGE_BYTES;
        const int k0 = koff + ck * BKC;
        {
            const uint32_t o = swz(fr0, fu0);
            const size_t ga = (size_t)fr0 * lda + k0 + fu0 * 8;
            const size_t gb = (size_t)fr0 * ldb + k0 + fu0 * 8;
            CP16(base + OFF_AH + o, pAh + ga);
            CP16(base + OFF_AL + o, pAl + ga);
            CP16(base + OFF_BH + o, pBh + gb);
            CP16(base + OFF_BL + o, pBl + gb);
        }
        {
            const uint32_t o = swz(fr1, fu1);
            const size_t ga = (size_t)fr1 * lda + k0 + fu1 * 8;
            const size_t gb = (size_t)fr1 * ldb + k0 + fu1 * 8;
            CP16(base + OFF_AH + o, pAh + ga);
            CP16(base + OFF_AL + o, pAl + ga);
            CP16(base + OFF_BH + o, pBh + gb);
            CP16(base + OFF_BL + o, pBl + gb);
        }
    };

    const int wm = wid >> 1;
    const int wn = (wid & 1) * 64;
    const int wr = wm * 32;

    float acc[2][8][4];
#pragma unroll
    for (int i = 0; i < 2; i++)
#pragma unroll
        for (int j = 0; j < 8; j++)
#pragma unroll
            for (int t = 0; t < 4; t++) acc[i][j][t] = 0.f;

    const int a_row = (lane & 15);
    const int a_ukx = (lane >> 4);
    const int b_row = ((lane >> 4) & 1) * 8 + (lane & 7);
    const int b_ukx = ((lane >> 3) & 1);

    fill(0, 0); CP_COMMIT();
    fill(1, 1); CP_COMMIT();

    for (int ck = 0; ck < nch; ck++) {
        CP_WAIT1();
        __syncthreads();
        if (ck + 2 < nch) fill((ck + 2) % STAGES, ck + 2);
        CP_COMMIT();

        const uint32_t base = sb + (ck % STAGES) * STAGE_BYTES;

#pragma unroll
        for (int ks = 0; ks < 2; ks++) {
            uint32_t ahf[2][4], alf[2][4];
#pragma unroll
            for (int mi = 0; mi < 2; mi++) {
                const uint32_t addr =
                    base + swz(wr + mi * 16 + a_row, 2 * ks + a_ukx);
                ldsm4(ahf[mi], OFF_AH + addr);
                ldsm4(alf[mi], OFF_AL + addr);
            }
            uint32_t bhf[2][4], blf[2][4];
            {
                const uint32_t a0 = base + swz(wn + b_row, 2 * ks + b_ukx);
                ldsm4(bhf[0], OFF_BH + a0);
                ldsm4(blf[0], OFF_BL + a0);
            }
#pragma unroll
            for (int np = 0; np < 4; np++) {
                const int cur = np & 1;
                if (np < 3) {
                    const uint32_t a1 =
                        base + swz(wn + (np + 1) * 16 + b_row, 2 * ks + b_ukx);
                    ldsm4(bhf[cur ^ 1], OFF_BH + a1);
                    ldsm4(blf[cur ^ 1], OFF_BL + a1);
                }
#pragma unroll
                for (int mi = 0; mi < 2; mi++) {
                    mma_bf16(acc[mi][np * 2 + 0], ahf[mi], bhf[cur][0], bhf[cur][1]);
                    mma_bf16(acc[mi][np * 2 + 0], ahf[mi], blf[cur][0], blf[cur][1]);
                    mma_bf16(acc[mi][np * 2 + 0], alf[mi], bhf[cur][0], bhf[cur][1]);
                    mma_bf16(acc[mi][np * 2 + 1], ahf[mi], bhf[cur][2], bhf[cur][3]);
                    mma_bf16(acc[mi][np * 2 + 1], ahf[mi], blf[cur][2], blf[cur][3]);
                    mma_bf16(acc[mi][np * 2 + 1], alf[mi], bhf[cur][2], bhf[cur][3]);
                }
            }
        }
    }

    // ---------------- epilogue ----------------
    if (MODE == 5) {
        __syncthreads();
        float* ts = (float*)smem;  // [128 cols][132 rows]
        const int lr = wr + (lane >> 2);
        const int lc = wn + ((lane & 3) << 1);
#pragma unroll
        for (int mi = 0; mi < 2; mi++) {
#pragma unroll
            for (int nb = 0; nb < 8; nb++) {
                const float* c = acc[mi][nb];
                const int col = lc + nb * 8;
                const int r0 = lr + mi * 16;
                const float2 b2 = *(const float2*)(bias_v + bn * 128 + col);
                ts[col * 132 + r0]           = c[0] + b2.x;
                ts[(col + 1) * 132 + r0]     = c[1] + b2.y;
                ts[col * 132 + r0 + 8]       = c[2] + b2.x;
                ts[(col + 1) * 132 + r0 + 8] = c[3] + b2.y;
            }
        }
        __syncthreads();
        const int m0 = bm * 128;
        const int b = m0 >> 11;
        const int s0 = m0 & (SEQ - 1);
        const size_t obase = (size_t)b * HID * SEQ + (size_t)(bn * 128) * SEQ + s0;
#pragma unroll
        for (int it = 0; it < 32; it++) {
            const int i2 = it * 256 + tid;
            const int h = i2 >> 6;
            const int sp = (i2 & 63) << 1;
            const float2 v = *(const float2*)&ts[h * 132 + sp];
            __nv_bfloat16 h0, l0, h1, l1;
            split1(v.x, h0, l0);
            split1(v.y, h1, l1);
            const size_t o = obase + (size_t)h * SEQ + sp;
            *(uint32_t*)(Vth + o) = pack2(h0, h1);
            *(uint32_t*)(Vtl + o) = pack2(l0, l1);
        }
        return;
    }

    const int rb = bm * 128 + wr + (lane >> 2);
    const int cb = bn * 128 + wn + ((lane & 3) << 1);

#pragma unroll
    for (int mi = 0; mi < 2; mi++) {
        const int r0 = rb + mi * 16;
        if (MODE == 6) {
            float* dst = Cf + (size_t)bz * EMB * EMB;
#pragma unroll
            for (int nb = 0; nb < 8; nb++) {
                const float* c = acc[mi][nb];
                const int col = cb + nb * 8;
                *(float2*)(dst + (size_t)r0 * ldc + col) = make_float2(c[0], c[1]);
                *(float2*)(dst + (size_t)(r0 + 8) * ldc + col) = make_float2(c[2], c[3]);
            }
        } else if (MODE == 2) {
            const float u0 = uvec[r0];
            const float u1 = uvec[r0 + 8];
#pragma unroll
            for (int nb = 0; nb < 8; nb++) {
                const float* c = acc[mi][nb];
                const int col = cb + nb * 8;
                const float2 w2 = *(const float2*)(wvec + col);
                *(float2*)(Cf + (size_t)r0 * ldc + col) =
                    make_float2((c[0] + u0 + w2.x) * scale,
                                (c[1] + u0 + w2.y) * scale);
                *(float2*)(Cf + (size_t)(r0 + 8) * ldc + col) =
                    make_float2((c[2] + u1 + w2.x) * scale,
                                (c[3] + u1 + w2.y) * scale);
            }
        } else if (MODE == 3) {
            const float is0 = invp[r0];
            const float is1 = invp[r0 + 8];
#pragma unroll
            for (int nb = 0; nb < 8; nb++) {
                const float* c = acc[mi][nb];
                const int col = cb + nb * 8;
                *(float2*)(Cf + (size_t)r0 * ldc + col) =
                    make_float2(c[0] * is0, c[1] * is0);
                *(float2*)(Cf + (size_t)(r0 + 8) * ldc + col) =
                    make_float2(c[2] * is1, c[3] * is1);
            }
        } else {  // MODE 0: bf16 hi/lo out
#pragma unroll
            for (int nb = 0; nb < 8; nb++) {
                const float* c = acc[mi][nb];
                const int col = cb + nb * 8;
                __nv_bfloat16 h0, l0, h1, l1;
                split1(c[0], h0, l0);
                split1(c[1], h1, l1);
                *(uint32_t*)(Chi + (size_t)r0 * ldc + col) = pack2(h0, h1);
                *(uint32_t*)(Clo + (size_t)r0 * ldc + col) = pack2(l0, l1);
                split1(c[2], h0, l0);
                split1(c[3], h1, l1);
                *(uint32_t*)(Chi + (size_t)(r0 + 8) * ldc + col) = pack2(h0, h1);
                *(uint32_t*)(Clo + (size_t)(r0 + 8) * ldc + col) = pack2(l0, l1);
            }
        }
    }
}

// ---------------------------------------------------------------------------
// prep_w: transpose+split Wq,Wk (2048 blocks)
// ---------------------------------------------------------------------------
__global__ __launch_bounds__(256)
void prep_w(const float* __restrict__ wq, const float* __restrict__ wk,
            __nv_bfloat16* __restrict__ qth, __nv_bfloat16* __restrict__ qtl,
            __nv_bfloat16* __restrict__ kth, __nv_bfloat16* __restrict__ ktl) {
    __shared__ float tbuf[32][33];
    const int j = blockIdx.x;
    const int z = j >> 10;
    const int rem = j & 1023;
    const int i0 = (rem & 31) * 32;
    const int h0 = (rem >> 5) * 32;
    const float* src = z ? wk : wq;
    __nv_bfloat16* dh = z ? kth : qth;
    __nv_bfloat16* dl = z ? ktl : qtl;
    const int tid = threadIdx.x;
    const int tx = tid & 31, ty = tid >> 5;
#pragma unroll
    for (int r = ty; r < 32; r += 8)
        tbuf[r][tx] = src[(size_t)(h0 + r) * EMB + i0 + tx];
    __syncthreads();
#pragma unroll
    for (int r = ty; r < 32; r += 8) {
        const float val = tbuf[tx][r];
        __nv_bfloat16 h, l;
        split1(val, h, l);
        const size_t o = (size_t)(i0 + r) * EMB + h0 + tx;
        dh[o] = h;
        dl[o] = l;
    }
}

// ---------------------------------------------------------------------------
// prep_x: split x and Wv into bf16 hi/lo
// ---------------------------------------------------------------------------
#define XN4 (MTOT * EMB / 4)
#define WN4 (HID * EMB / 4)

__global__ __launch_bounds__(256)
void prep_x(const float4* __restrict__ x, const float4* __restrict__ wv,
            uint2* __restrict__ xh, uint2* __restrict__ xl,
            uint2* __restrict__ wvh, uint2* __restrict__ wvl) {
    const int id = blockIdx.x * 256 + threadIdx.x;
    const float4* src;
    uint2 *dh, *dl;
    int i;
    if (id < XN4) { src = x; dh = xh; dl = xl; i = id; }
    else          { src = wv; dh = wvh; dl = wvl; i = id - XN4; }
    const float4 v = src[i];
    __nv_bfloat16 h0, l0, h1, l1, h2, l2, h3, l3;
    split1(v.x, h0, l0); split1(v.y, h1, l1);
    split1(v.z, h2, l2); split1(v.w, h3, l3);
    dh[i] = make_uint2(pack2(h0, h1), pack2(h2, h3));
    dl[i] = make_uint2(pack2(l0, l1), pack2(l2, l3));
}

// ---------------------------------------------------------------------------
// Reduce the 8 Mt split-K partials (fixed order), emit bf16 hi/lo
// ---------------------------------------------------------------------------
__global__ __launch_bounds__(256)
void reduce_mt(const float4* __restrict__ mp, uint2* __restrict__ mth,
               uint2* __restrict__ mtl) {
    const int i = blockIdx.x * 256 + threadIdx.x;
    float4 s = mp[i];
#pragma unroll
    for (int p = 1; p < 8; p++) {
        const float4 v = mp[(size_t)p * (EMB * EMB / 4) + i];
        s.x += v.x; s.y += v.y; s.z += v.z; s.w += v.w;
    }
    __nv_bfloat16 h0, l0, h1, l1, h2, l2, h3, l3;
    split1(s.x, h0, l0); split1(s.y, h1, l1);
    split1(s.z, h2, l2); split1(s.w, h3, l3);
    mth[i] = make_uint2(pack2(h0, h1), pack2(h2, h3));
    mtl[i] = make_uint2(pack2(l0, l1), pack2(l2, l3));
}

// ---------------------------------------------------------------------------
// r1[i] = Wq^T bk, r2[i] = Wk^T bq, c = bq.bk
// ---------------------------------------------------------------------------
__global__ __launch_bounds__(256)
void bias_vec(const __nv_bfloat16* __restrict__ qth, const __nv_bfloat16* __restrict__ qtl,
              const __nv_bfloat16* __restrict__ kth, const __nv_bfloat16* __restrict__ ktl,
              const float* __restrict__ bq, const float* __restrict__ bk,
              float* __restrict__ r1, float* __restrict__ r2, float* __restrict__ cp) {
    const int tid = threadIdx.x;
    if (blockIdx.x == 128) {
        __shared__ float red[8];
        float s = 0.f;
        for (int h = tid; h < EMB; h += 256) s += bq[h] * bk[h];
#pragma unroll
        for (int o = 16; o > 0; o >>= 1) s += __shfl_xor_sync(0xffffffffu, s, o);
        if ((tid & 31) == 0) red[tid >> 5] = s;
        __syncthreads();
        if (tid < 8) {
            s = red[tid];
#pragma unroll
            for (int o = 4; o > 0; o >>= 1) s += __shfl_xor_sync(0xffu, s, o);
            if (tid == 0) cp[0] = s;
        }
        return;
    }
    const int lane = tid & 31;
    const int row = blockIdx.x * 8 + (tid >> 5);
    float s1 = 0.f, s2 = 0.f;
    for (int h = lane; h < EMB; h += 32) {
        const size_t o = (size_t)row * EMB + h;
        s1 += (__bfloat162float(qth[o]) + __bfloat162float(qtl[o])) * bk[h];
        s2 += (__bfloat162float(kth[o]) + __bfloat162float(ktl[o])) * bq[h];
    }
#pragma unroll
    for (int o = 16; o > 0; o >>= 1) {
        s1 += __shfl_xor_sync(0xffffffffu, s1, o);
        s2 += __shfl_xor_sync(0xffffffffu, s2, o);
    }
    if (lane == 0) { r1[row] = s1; r2[row] = s2; }
}

// ---------------------------------------------------------------------------
// u[q] = x[q,:].r1 + c ;  w[q] = x[q,:].r2
// ---------------------------------------------------------------------------
__global__ __launch_bounds__(256)
void gemv_uw(const float* __restrict__ x, const float* __restrict__ r1,
             const float* __restrict__ r2, const float* __restrict__ cp,
             float* __restrict__ u, float* __restrict__ w) {
    const int tid = threadIdx.x;
    const int lane = tid & 31;
    const int q = blockIdx.x * 8 + (tid >> 5);
    float s1 = 0.f, s2 = 0.f;
    const float* xr = x + (size_t)q * EMB;
    for (int i = lane; i < EMB; i += 32) {
        const float xv = xr[i];
        s1 = fmaf(xv, r1[i], s1);
        s2 = fmaf(xv, r2[i], s2);
    }
#pragma unroll
    for (int o = 16; o > 0; o >>= 1) {
        s1 += __shfl_xor_sync(0xffffffffu, s1, o);
        s2 += __shfl_xor_sync(0xffffffffu, s2, o);
    }
    if (lane == 0) { u[q] = s1 + cp[0]; w[q] = s2; }
}

// ---------------------------------------------------------------------------
// Single-pass softmax for ONE batch (pointers pre-offset): grid = SEQ blocks
// ---------------------------------------------------------------------------
__global__ __launch_bounds__(256)
void softmax_pass(const float* __restrict__ S, __nv_bfloat16* __restrict__ ah,
                  __nv_bfloat16* __restrict__ al, float* __restrict__ invp) {
    const int q = blockIdx.x;           // row within batch
    const float* p = S + (size_t)q * SEQ;
    const int len = q + 1;
    const int tid = threadIdx.x;
    const size_t base = (size_t)q * SEQ;
    __shared__ float red[32];

    float s = 0.f;
    const int n4 = len >> 2;
    const float4* p4 = (const float4*)p;
    uint2* ah2 = (uint2*)(ah + base);
    uint2* al2 = (uint2*)(al + base);
    for (int i = tid; i < n4; i += 256) {
        const float4 v = p4[i];
        const float e0 = fexp(v.x), e1 = fexp(v.y), e2 = fexp(v.z), e3 = fexp(v.w);
        s += (e0 + e1) + (e2 + e3);
        __nv_bfloat16 h0, l0, h1, l1, h2, l2, h3, l3;
        split1(e0, h0, l0); split1(e1, h1, l1);
        split1(e2, h2, l2); split1(e3, h3, l3);
        ah2[i] = make_uint2(pack2(h0, h1), pack2(h2, h3));
        al2[i] = make_uint2(pack2(l0, l1), pack2(l2, l3));
    }
    for (int k = (n4 << 2) + tid; k < len; k += 256) {
        const float e = fexp(p[k]);
        s += e;
        __nv_bfloat16 h, l;
        split1(e, h, l);
        ah[base + k] = h;
        al[base + k] = l;
    }

#pragma unroll
    for (int o = 16; o > 0; o >>= 1) s += __shfl_xor_sync(0xffffffffu, s, o);
    if ((tid & 31) == 0) red[tid >> 5] = s;
    __syncthreads();
    s = red[tid & 7];
#pragma unroll
    for (int o = 4; o > 0; o >>= 1) s += __shfl_xor_sync(0xffffffffu, s, o);
    if (tid == 0) invp[q] = 1.0f / s;

    const int zend = ((q >> 7) + 1) << 7;
    const __nv_bfloat16 z = __float2bfloat16_rn(0.f);
    for (int k = len + tid; k < zend; k += 256) {
        ah[base + k] = z;
        al[base + k] = z;
    }
}

// ---------------------------------------------------------------------------
extern "C" void kernel_launch(void* const* d_in, const int* in_sizes, int n_in,
                              void* d_out, int out_size) {
    const float* x  = (const float*)d_in[0];
    const float* Wq = (const float*)d_in[1];
    const float* bq = (const float*)d_in[2];
    const float* Wk = (const float*)d_in[3];
    const float* bk = (const float*)d_in[4];
    const float* Wv = (const float*)d_in[5];
    const float* bv = (const float*)d_in[6];
    float* out = (float*)d_out;

    __nv_bfloat16 *xh, *xl, *wvh, *wvl, *qth, *qtl, *kth, *ktl;
    __nv_bfloat16 *mth, *mtl, *th, *tl, *vth, *vtl, *ah, *al;
    float *mp, *s, *inv, *r1, *r2, *c, *u, *w;
    cudaGetSymbolAddress((void**)&xh, g_xh);     cudaGetSymbolAddress((void**)&xl, g_xl);
    cudaGetSymbolAddress((void**)&wvh, g_wvh);   cudaGetSymbolAddress((void**)&wvl, g_wvl);
    cudaGetSymbolAddress((void**)&qth, g_wqth);  cudaGetSymbolAddress((void**)&qtl, g_wqtl);
    cudaGetSymbolAddress((void**)&kth, g_wkth);  cudaGetSymbolAddress((void**)&ktl, g_wktl);
    cudaGetSymbolAddress((void**)&mp, g_mp);
    cudaGetSymbolAddress((void**)&mth, g_mth);   cudaGetSymbolAddress((void**)&mtl, g_mtl);
    cudaGetSymbolAddress((void**)&th, g_th);     cudaGetSymbolAddress((void**)&tl, g_tl);
    cudaGetSymbolAddress((void**)&vth, g_vth);   cudaGetSymbolAddress((void**)&vtl, g_vtl);
    cudaGetSymbolAddress((void**)&ah, g_ah);     cudaGetSymbolAddress((void**)&al, g_al);
    cudaGetSymbolAddress((void**)&s, g_s);       cudaGetSymbolAddress((void**)&inv, g_inv);
    cudaGetSymbolAddress((void**)&r1, g_r1);     cudaGetSymbolAddress((void**)&r2, g_r2);
    cudaGetSymbolAddress((void**)&c, g_c);
    cudaGetSymbolAddress((void**)&u, g_u);       cudaGetSymbolAddress((void**)&w, g_w);

    cudaFuncSetAttribute(gemm_tc<0>, cudaFuncAttributeMaxDynamicSharedMemorySize, GEMM_SMEM);
    cudaFuncSetAttribute(gemm_tc<5>, cudaFuncAttributeMaxDynamicSharedMemorySize, GEMM_SMEM);
    cudaFuncSetAttribute(gemm_tc<6>, cudaFuncAttributeMaxDynamicSharedMemorySize, GEMM_SMEM);
    cudaFuncSetAttribute(gemm_tc<2>, cudaFuncAttributeMaxDynamicSharedMemorySize, GEMM_SMEM);
    cudaFuncSetAttribute(gemm_tc<3>, cudaFuncAttributeMaxDynamicSharedMemorySize, GEMM_SMEM);

    cudaStream_t s2, s3;
    cudaStreamCreate(&s2);
    cudaStreamCreate(&s3);
    cudaEvent_t ev_w, ev_px, ev_red, ev_uw, ev_sc[BATCH], ev_sm[BATCH], ev_join;
    cudaEventCreateWithFlags(&ev_w, cudaEventDisableTiming);
    cudaEventCreateWithFlags(&ev_px, cudaEventDisableTiming);
    cudaEventCreateWithFlags(&ev_red, cudaEventDisableTiming);
    cudaEventCreateWithFlags(&ev_uw, cudaEventDisableTiming);
    cudaEventCreateWithFlags(&ev_join, cudaEventDisableTiming);
    for (int b = 0; b < BATCH; b++) {
        cudaEventCreateWithFlags(&ev_sc[b], cudaEventDisableTiming);
        cudaEventCreateWithFlags(&ev_sm[b], cudaEventDisableTiming);
    }

    // ---- main: weight transposes first (tiny) to unblock Mt + bias
    prep_w<<<2048, 256>>>(Wq, Wk, qth, qtl, kth, ktl);
    cudaEventRecord(ev_w, 0);

    // ---- s3 (tensor): Mt split-K + reduce, overlapping main's prep_x
    cudaStreamWaitEvent(s3, ev_w, 0);
    gemm_tc<6><<<dim3(8, 8, 8), 256, GEMM_SMEM, s3>>>(
        kth, ktl, qth, qtl, nullptr,
        mp, nullptr, nullptr, nullptr, nullptr,
        nullptr, nullptr, nullptr,
        EMB, EMB, EMB, EMB, 1.f);
    reduce_mt<<<EMB * EMB / 4 / 256, 256, 0, s3>>>(
        (const float4*)mp, (uint2*)mth, (uint2*)mtl);
    cudaEventRecord(ev_red, s3);

    // ---- s2 (memory): bias -> gemv; then V projection after prep_x
    cudaStreamWaitEvent(s2, ev_w, 0);
    bias_vec<<<129, 256, 0, s2>>>(qth, qtl, kth, ktl, bq, bk, r1, r2, c);
    gemv_uw<<<MTOT / 8, 256, 0, s2>>>(x, r1, r2, c, u, w);
    cudaEventRecord(ev_uw, s2);

    // ---- main (memory): split x + Wv, overlapping s3's Mt
    prep_x<<<(XN4 + WN4) / 256, 256>>>(
        (const float4*)x, (const float4*)Wv,
        (uint2*)xh, (uint2*)xl, (uint2*)wvh, (uint2*)wvl);
    cudaEventRecord(ev_px, 0);

    // ---- s2: V projection (needs prep_x); AV batches follow on s2 (stream
    //      order makes the V dependency implicit)
    cudaStreamWaitEvent(s2, ev_px, 0);
    gemm_tc<5><<<dim3(HID / 128, MTOT / 128), 256, GEMM_SMEM, s2>>>(
        xh, xl, wvh, wvl, bv, nullptr, nullptr, nullptr,
        vth, vtl, nullptr, nullptr, nullptr,
        EMB, EMB, EMB, HID, 1.f);

    // ---- main: needs Mt + scores need u/w once
    cudaStreamWaitEvent(0, ev_red, 0);
    cudaStreamWaitEvent(0, ev_uw, 0);

    // ---- per-batch pipeline: t_b -> scores_b (main); softmax_b (s3); AV_b (s2)
    for (int b = 0; b < BATCH; b++) {
        const size_t xoff = (size_t)b * SEQ * EMB;
        const size_t soff = (size_t)b * SEQ * SEQ;

        gemm_tc<0><<<dim3(EMB / 128, SEQ / 128), 256, GEMM_SMEM>>>(
            xh + xoff, xl + xoff, mth, mtl, nullptr,
            nullptr, th + xoff, tl + xoff, nullptr, nullptr,
            nullptr, nullptr, nullptr,
            EMB, EMB, EMB, EMB, 1.f);

        gemm_tc<2><<<N_TRI, 256, GEMM_SMEM>>>(
            th + xoff, tl + xoff, xh + xoff, xl + xoff, nullptr,
            s + soff, nullptr, nullptr, nullptr, nullptr,
            u + b * SEQ, w + b * SEQ, nullptr,
            EMB, EMB, EMB, SEQ, 0.03125f);
        cudaEventRecord(ev_sc[b], 0);

        cudaStreamWaitEvent(s3, ev_sc[b], 0);
        softmax_pass<<<SEQ, 256, 0, s3>>>(s + soff, ah + soff, al + soff,
                                          inv + b * SEQ);
        cudaEventRecord(ev_sm[b], s3);

        cudaStreamWaitEvent(s2, ev_sm[b], 0);
        gemm_tc<3><<<dim3(HID / 128, SEQ / 128), 256, GEMM_SMEM, s2>>>(
            ah + soff, al + soff,
            vth + (size_t)b * HID * SEQ, vtl + (size_t)b * HID * SEQ, nullptr,
            out + xoff, nullptr, nullptr, nullptr, nullptr,
            nullptr, nullptr, inv + b * SEQ,
            SEQ, SEQ, SEQ, HID, 1.f);
    }

    // join all streams back to main for capture legality
    cudaEventRecord(ev_join, s2);
    cudaStreamWaitEvent(0, ev_join, 0);

    // cleanup only outside capture
    cudaStreamCaptureStatus cs = cudaStreamCaptureStatusNone;
    cudaStreamIsCapturing(s2, &cs);
    if (cs == cudaStreamCaptureStatusNone) {
        cudaStreamDestroy(s2);
        cudaStreamDestroy(s3);
        cudaEventDestroy(ev_w);
        cudaEventDestroy(ev_px);
        cudaEventDestroy(ev_red);
        cudaEventDestroy(ev_uw);
        cudaEventDestroy(ev_join);
        for (int b = 0; b < BATCH; b++) {
            cudaEventDestroy(ev_sc[b]);
            cudaEventDestroy(ev_sm[b]);
        }
    }
}

// round 15
// speedup vs baseline: 1.3270x; 1.3270x over previous
#include <cuda_runtime.h>
#include <cuda_bf16.h>
#include <math.h>
#include <stdint.h>

#define BATCH 4
#define SEQ   2048
#define EMB   1024
#define HID   1024
#define MTOT  (BATCH * SEQ)

// ---------------------------------------------------------------------------
// Device-global scratch
// ---------------------------------------------------------------------------
__device__ __nv_bfloat16 g_xh[MTOT * EMB], g_xl[MTOT * EMB];
__device__ __nv_bfloat16 g_wvh[HID * EMB], g_wvl[HID * EMB];
__device__ __nv_bfloat16 g_wqth[EMB * HID], g_wqtl[EMB * HID];  // Wq^T
__device__ __nv_bfloat16 g_wkth[EMB * HID], g_wktl[EMB * HID];  // Wk^T
__device__ float         g_mp[8 * 1024 * 1024];                 // Mt split-K partials
__device__ __nv_bfloat16 g_mth[EMB * EMB], g_mtl[EMB * EMB];    // Mt = (WqT Wk)^T layout
__device__ __nv_bfloat16 g_th[MTOT * EMB], g_tl[MTOT * EMB];    // t = x M
__device__ __nv_bfloat16 g_vth[BATCH * HID * SEQ], g_vtl[BATCH * HID * SEQ];
__device__ float         g_s [(size_t)BATCH * SEQ * SEQ];
__device__ __nv_bfloat16 g_ah[(size_t)BATCH * SEQ * SEQ];
__device__ __nv_bfloat16 g_al[(size_t)BATCH * SEQ * SEQ];
__device__ float         g_inv[MTOT];
__device__ float         g_r1[EMB], g_r2[EMB], g_c[1];
__device__ float         g_u[MTOT], g_w[MTOT];

// ---------------------------------------------------------------------------
// Helpers
// ---------------------------------------------------------------------------
__device__ __forceinline__ uint32_t smem_u32(const void* p) {
    uint32_t a;
    asm("{ .reg .u64 t; cvta.to.shared.u64 t, %1; cvt.u32.u64 %0, t; }"
        : "=r"(a) : "l"(p));
    return a;
}

__device__ __forceinline__ uint32_t pack2(__nv_bfloat16 a, __nv_bfloat16 b) {
    __nv_bfloat162 t = __halves2bfloat162(a, b);
    return *reinterpret_cast<uint32_t*>(&t);
}

__device__ __forceinline__ void split1(float v, __nv_bfloat16& h, __nv_bfloat16& l) {
    h = __float2bfloat16_rn(v);
    l = __float2bfloat16_rn(v - __bfloat162float(h));
}

// FMA-pipe exp (degree-6 2^f poly, rel err ~1.2e-7)
__device__ __forceinline__ float fexp(float x) {
    x = fminf(fmaxf(x, -87.f), 87.f);
    const float t = x * 1.4426950408889634f;
    const int i = __float2int_rn(t);
    const float f = t - (float)i;
    float p = 1.54035304e-4f;
    p = fmaf(p, f, 1.33335581e-3f);
    p = fmaf(p, f, 9.61812910e-3f);
    p = fmaf(p, f, 5.55041086e-2f);
    p = fmaf(p, f, 2.40226462e-1f);
    p = fmaf(p, f, 6.93147182e-1f);
    p = fmaf(p, f, 1.0f);
    return p * __int_as_float((i + 127) << 23);
}

#define CP16(dst, src)                                                         \
    asm volatile("cp.async.cg.shared.global [%0], [%1], 16;" ::"r"(dst),       \
                 "l"(src))
#define CP_COMMIT() asm volatile("cp.async.commit_group;" ::: "memory")
#define CP_WAIT1()  asm volatile("cp.async.wait_group 1;" ::: "memory")

__device__ __forceinline__ void ldsm4(uint32_t* r, uint32_t addr) {
    asm volatile(
        "ldmatrix.sync.aligned.m8n8.x4.shared.b16 {%0,%1,%2,%3}, [%4];"
        : "=r"(r[0]), "=r"(r[1]), "=r"(r[2]), "=r"(r[3])
        : "r"(addr));
}

__device__ __forceinline__ void mma_bf16(float* c, const uint32_t* a,
                                         uint32_t b0, uint32_t b1) {
    asm volatile(
        "mma.sync.aligned.m16n8k16.row.col.f32.bf16.bf16.f32 "
        "{%0,%1,%2,%3}, {%4,%5,%6,%7}, {%8,%9}, {%0,%1,%2,%3};"
        : "+f"(c[0]), "+f"(c[1]), "+f"(c[2]), "+f"(c[3])
        : "r"(a[0]), "r"(a[1]), "r"(a[2]), "r"(a[3]), "r"(b0), "r"(b1));
}

__device__ __forceinline__ uint32_t swz(int row, int unit) {
    return (uint32_t)(row * 64 + ((unit ^ ((row >> 1) & 3)) << 4));
}

// ---------------------------------------------------------------------------
// bf16x3 emulated-fp32 GEMM via mma.sync (NT): D[m,n] = sum_k A[m,k]*B[n,k]
// (mainloop = the proven R11 form: per-np B double-buffering, hh/hl/lh triple)
// MODE 0: plain bf16 hi/lo out                        (t = x·M)
// MODE 5: V projection (+bias), transpose epilogue -> [b][h][s] bf16 hi/lo
// MODE 6: Mt split-K partials (bz = K-part, fp32 partial out)
// MODE 2: scores = t·x^T + u[q] + w[k], *scale, fp32 out, triangular grid
// MODE 3: attn @ V^T; per-row inv[] normalization, K truncated causally
// ---------------------------------------------------------------------------
#define BKC 32
#define STAGES 3
#define STAGE_BYTES (4 * 128 * BKC * 2)
#define GEMM_SMEM (STAGES * STAGE_BYTES)
#define OFF_AH 0
#define OFF_AL (128 * BKC * 2)
#define OFF_BH (2 * 128 * BKC * 2)
#define OFF_BL (3 * 128 * BKC * 2)

#define N_TRI 136   // 16*17/2 score tiles per batch

template <int MODE>
__global__ __launch_bounds__(256, 2)
void gemm_tc(const __nv_bfloat16* __restrict__ Ah, const __nv_bfloat16* __restrict__ Al,
             const __nv_bfloat16* __restrict__ Bh, const __nv_bfloat16* __restrict__ Bl,
             const float* __restrict__ bias_v,
             float* __restrict__ Cf,
             __nv_bfloat16* __restrict__ Chi, __nv_bfloat16* __restrict__ Clo,
             __nv_bfloat16* __restrict__ Vth, __nv_bfloat16* __restrict__ Vtl,
             const float* __restrict__ uvec, const float* __restrict__ wvec,
             const float* __restrict__ invp,
             int K, int lda, int ldb, int ldc,
             size_t strA, size_t strB, size_t strC, float scale) {
    int bm, bn, bz = 0;
    int koff = 0;
    if (MODE == 2) {
        const int t0 = blockIdx.x;
        int t = (int)((sqrtf(8.f * t0 + 1.f) - 1.f) * 0.5f);
        while ((t + 1) * (t + 2) / 2 <= t0) t++;
        while (t * (t + 1) / 2 > t0) t--;
        bm = t;
        bn = t0 - t * (t + 1) / 2;
        bz = blockIdx.z;
    } else if (MODE == 3) {
        bn = blockIdx.x;
        bm = gridDim.y - 1 - blockIdx.y;  // heavy rows first
        bz = blockIdx.z;
    } else if (MODE == 6) {
        bn = blockIdx.x;
        bm = blockIdx.y;
        bz = blockIdx.z;        // K-part
        koff = bz * 128;        // 4 chunks of 32
    } else {                    // MODE 0 / 5
        bn = blockIdx.x;
        bm = blockIdx.y;
    }

    extern __shared__ __align__(1024) char smem[];
    const uint32_t sb = smem_u32(smem);

    const int tid = threadIdx.x;
    const int wid = tid >> 5, lane = tid & 31;

    const __nv_bfloat16* pAh = Ah + strA * bz + (size_t)bm * 128 * lda;
    const __nv_bfloat16* pAl = Al + strA * bz + (size_t)bm * 128 * lda;
    const __nv_bfloat16* pBh = Bh + strB * bz + (size_t)bn * 128 * ldb;
    const __nv_bfloat16* pBl = Bl + strB * bz + (size_t)bn * 128 * ldb;

    int nch = K / BKC;
    if (MODE == 3) nch = 4 * (bm + 1);
    if (MODE == 6) nch = 4;

    const int fr0 = tid >> 2, fu0 = tid & 3;
    const int fr1 = (tid + 256) >> 2, fu1 = tid & 3;

    auto fill = [&](int stage, int ck) {
        const uint32_t base = sb + stage * STAGE_BYTES;
        const int k0 = koff + ck * BKC;
        {
            const uint32_t o = swz(fr0, fu0);
            const size_t ga = (size_t)fr0 * lda + k0 + fu0 * 8;
            const size_t gb = (size_t)fr0 * ldb + k0 + fu0 * 8;
            CP16(base + OFF_AH + o, pAh + ga);
            CP16(base + OFF_AL + o, pAl + ga);
            CP16(base + OFF_BH + o, pBh + gb);
            CP16(base + OFF_BL + o, pBl + gb);
        }
        {
            const uint32_t o = swz(fr1, fu1);
            const size_t ga = (size_t)fr1 * lda + k0 + fu1 * 8;
            const size_t gb = (size_t)fr1 * ldb + k0 + fu1 * 8;
            CP16(base + OFF_AH + o, pAh + ga);
            CP16(base + OFF_AL + o, pAl + ga);
            CP16(base + OFF_BH + o, pBh + gb);
            CP16(base + OFF_BL + o, pBl + gb);
        }
    };

    const int wm = wid >> 1;
    const int wn = (wid & 1) * 64;
    const int wr = wm * 32;

    float acc[2][8][4];
#pragma unroll
    for (int i = 0; i < 2; i++)
#pragma unroll
        for (int j = 0; j < 8; j++)
#pragma unroll
            for (int t = 0; t < 4; t++) acc[i][j][t] = 0.f;

    const int a_row = (lane & 15);
    const int a_ukx = (lane >> 4);
    const int b_row = ((lane >> 4) & 1) * 8 + (lane & 7);
    const int b_ukx = ((lane >> 3) & 1);

    fill(0, 0); CP_COMMIT();
    fill(1, 1); CP_COMMIT();

    for (int ck = 0; ck < nch; ck++) {
        CP_WAIT1();
        __syncthreads();
        if (ck + 2 < nch) fill((ck + 2) % STAGES, ck + 2);
        CP_COMMIT();

        const uint32_t base = sb + (ck % STAGES) * STAGE_BYTES;

#pragma unroll
        for (int ks = 0; ks < 2; ks++) {
            uint32_t ahf[2][4], alf[2][4];
#pragma unroll
            for (int mi = 0; mi < 2; mi++) {
                const uint32_t addr =
                    base + swz(wr + mi * 16 + a_row, 2 * ks + a_ukx);
                ldsm4(ahf[mi], OFF_AH + addr);
                ldsm4(alf[mi], OFF_AL + addr);
            }
            uint32_t bhf[2][4], blf[2][4];
            {
                const uint32_t a0 = base + swz(wn + b_row, 2 * ks + b_ukx);
                ldsm4(bhf[0], OFF_BH + a0);
                ldsm4(blf[0], OFF_BL + a0);
            }
#pragma unroll
            for (int np = 0; np < 4; np++) {
                const int cur = np & 1;
                if (np < 3) {
                    const uint32_t a1 =
                        base + swz(wn + (np + 1) * 16 + b_row, 2 * ks + b_ukx);
                    ldsm4(bhf[cur ^ 1], OFF_BH + a1);
                    ldsm4(blf[cur ^ 1], OFF_BL + a1);
                }
#pragma unroll
                for (int mi = 0; mi < 2; mi++) {
                    mma_bf16(acc[mi][np * 2 + 0], ahf[mi], bhf[cur][0], bhf[cur][1]);
                    mma_bf16(acc[mi][np * 2 + 0], ahf[mi], blf[cur][0], blf[cur][1]);
                    mma_bf16(acc[mi][np * 2 + 0], alf[mi], bhf[cur][0], bhf[cur][1]);
                    mma_bf16(acc[mi][np * 2 + 1], ahf[mi], bhf[cur][2], bhf[cur][3]);
                    mma_bf16(acc[mi][np * 2 + 1], ahf[mi], blf[cur][2], blf[cur][3]);
                    mma_bf16(acc[mi][np * 2 + 1], alf[mi], bhf[cur][2], bhf[cur][3]);
                }
            }
        }
    }

    // ---------------- epilogue ----------------
    if (MODE == 5) {
        __syncthreads();
        float* ts = (float*)smem;  // [128 cols][132 rows]
        const int lr = wr + (lane >> 2);
        const int lc = wn + ((lane & 3) << 1);
#pragma unroll
        for (int mi = 0; mi < 2; mi++) {
#pragma unroll
            for (int nb = 0; nb < 8; nb++) {
                const float* c = acc[mi][nb];
                const int col = lc + nb * 8;
                const int r0 = lr + mi * 16;
                const float2 b2 = *(const float2*)(bias_v + bn * 128 + col);
                ts[col * 132 + r0]           = c[0] + b2.x;
                ts[(col + 1) * 132 + r0]     = c[1] + b2.y;
                ts[col * 132 + r0 + 8]       = c[2] + b2.x;
                ts[(col + 1) * 132 + r0 + 8] = c[3] + b2.y;
            }
        }
        __syncthreads();
        const int m0 = bm * 128;
        const int b = m0 >> 11;
        const int s0 = m0 & (SEQ - 1);
        const size_t obase = (size_t)b * HID * SEQ + (size_t)(bn * 128) * SEQ + s0;
#pragma unroll
        for (int it = 0; it < 32; it++) {
            const int i2 = it * 256 + tid;
            const int h = i2 >> 6;
            const int sp = (i2 & 63) << 1;
            const float2 v = *(const float2*)&ts[h * 132 + sp];
            __nv_bfloat16 h0, l0, h1, l1;
            split1(v.x, h0, l0);
            split1(v.y, h1, l1);
            const size_t o = obase + (size_t)h * SEQ + sp;
            *(uint32_t*)(Vth + o) = pack2(h0, h1);
            *(uint32_t*)(Vtl + o) = pack2(l0, l1);
        }
        return;
    }

    const int rb = bm * 128 + wr + (lane >> 2);
    const int cb = bn * 128 + wn + ((lane & 3) << 1);

#pragma unroll
    for (int mi = 0; mi < 2; mi++) {
        const int r0 = rb + mi * 16;
        if (MODE == 6) {
            float* dst = Cf + (size_t)bz * EMB * EMB;
#pragma unroll
            for (int nb = 0; nb < 8; nb++) {
                const float* c = acc[mi][nb];
                const int col = cb + nb * 8;
                *(float2*)(dst + (size_t)r0 * ldc + col) = make_float2(c[0], c[1]);
                *(float2*)(dst + (size_t)(r0 + 8) * ldc + col) = make_float2(c[2], c[3]);
            }
        } else if (MODE == 2) {
            const float u0 = uvec[bz * SEQ + r0];
            const float u1 = uvec[bz * SEQ + r0 + 8];
            float* dst = Cf + strC * bz;
#pragma unroll
            for (int nb = 0; nb < 8; nb++) {
                const float* c = acc[mi][nb];
                const int col = cb + nb * 8;
                const float2 w2 = *(const float2*)(wvec + bz * SEQ + col);
                *(float2*)(dst + (size_t)r0 * ldc + col) =
                    make_float2((c[0] + u0 + w2.x) * scale,
                                (c[1] + u0 + w2.y) * scale);
                *(float2*)(dst + (size_t)(r0 + 8) * ldc + col) =
                    make_float2((c[2] + u1 + w2.x) * scale,
                                (c[3] + u1 + w2.y) * scale);
            }
        } else if (MODE == 3) {
            const float is0 = invp[bz * SEQ + r0];
            const float is1 = invp[bz * SEQ + r0 + 8];
            float* dst = Cf + strC * bz;
#pragma unroll
            for (int nb = 0; nb < 8; nb++) {
                const float* c = acc[mi][nb];
                const int col = cb + nb * 8;
                *(float2*)(dst + (size_t)r0 * ldc + col) =
                    make_float2(c[0] * is0, c[1] * is0);
                *(float2*)(dst + (size_t)(r0 + 8) * ldc + col) =
                    make_float2(c[2] * is1, c[3] * is1);
            }
        } else {  // MODE 0: bf16 hi/lo out
#pragma unroll
            for (int nb = 0; nb < 8; nb++) {
                const float* c = acc[mi][nb];
                const int col = cb + nb * 8;
                __nv_bfloat16 h0, l0, h1, l1;
                split1(c[0], h0, l0);
                split1(c[1], h1, l1);
                *(uint32_t*)(Chi + (size_t)r0 * ldc + col) = pack2(h0, h1);
                *(uint32_t*)(Clo + (size_t)r0 * ldc + col) = pack2(l0, l1);
                split1(c[2], h0, l0);
                split1(c[3], h1, l1);
                *(uint32_t*)(Chi + (size_t)(r0 + 8) * ldc + col) = pack2(h0, h1);
                *(uint32_t*)(Clo + (size_t)(r0 + 8) * ldc + col) = pack2(l0, l1);
            }
        }
    }
}

// ---------------------------------------------------------------------------
// prep_w: transpose+split Wq,Wk (2048 blocks) — small, unblocks Mt & bias fast
// ---------------------------------------------------------------------------
__global__ __launch_bounds__(256)
void prep_w(const float* __restrict__ wq, const float* __restrict__ wk,
            __nv_bfloat16* __restrict__ qth, __nv_bfloat16* __restrict__ qtl,
            __nv_bfloat16* __restrict__ kth, __nv_bfloat16* __restrict__ ktl) {
    __shared__ float tbuf[32][33];
    const int j = blockIdx.x;           // 0..2047
    const int z = j >> 10;              // 0 = Wq, 1 = Wk
    const int rem = j & 1023;
    const int i0 = (rem & 31) * 32;
    const int h0 = (rem >> 5) * 32;
    const float* src = z ? wk : wq;
    __nv_bfloat16* dh = z ? kth : qth;
    __nv_bfloat16* dl = z ? ktl : qtl;
    const int tid = threadIdx.x;
    const int tx = tid & 31, ty = tid >> 5;
#pragma unroll
    for (int r = ty; r < 32; r += 8)
        tbuf[r][tx] = src[(size_t)(h0 + r) * EMB + i0 + tx];
    __syncthreads();
#pragma unroll
    for (int r = ty; r < 32; r += 8) {
        const float val = tbuf[tx][r];
        __nv_bfloat16 h, l;
        split1(val, h, l);
        const size_t o = (size_t)(i0 + r) * EMB + h0 + tx;
        dh[o] = h;
        dl[o] = l;
    }
}

// ---------------------------------------------------------------------------
// prep_x: split x and Wv into bf16 hi/lo (flat, memory-bound)
// ---------------------------------------------------------------------------
#define XN4 (MTOT * EMB / 4)
#define WN4 (HID * EMB / 4)

__global__ __launch_bounds__(256)
void prep_x(const float4* __restrict__ x, const float4* __restrict__ wv,
            uint2* __restrict__ xh, uint2* __restrict__ xl,
            uint2* __restrict__ wvh, uint2* __restrict__ wvl) {
    const int id = blockIdx.x * 256 + threadIdx.x;
    const float4* src;
    uint2 *dh, *dl;
    int i;
    if (id < XN4) { src = x; dh = xh; dl = xl; i = id; }
    else          { src = wv; dh = wvh; dl = wvl; i = id - XN4; }
    const float4 v = src[i];
    __nv_bfloat16 h0, l0, h1, l1, h2, l2, h3, l3;
    split1(v.x, h0, l0); split1(v.y, h1, l1);
    split1(v.z, h2, l2); split1(v.w, h3, l3);
    dh[i] = make_uint2(pack2(h0, h1), pack2(h2, h3));
    dl[i] = make_uint2(pack2(l0, l1), pack2(l2, l3));
}

// ---------------------------------------------------------------------------
// Reduce the 8 Mt split-K partials (fixed order), emit bf16 hi/lo
// ---------------------------------------------------------------------------
__global__ __launch_bounds__(256)
void reduce_mt(const float4* __restrict__ mp, uint2* __restrict__ mth,
               uint2* __restrict__ mtl) {
    const int i = blockIdx.x * 256 + threadIdx.x;
    float4 s = mp[i];
#pragma unroll
    for (int p = 1; p < 8; p++) {
        const float4 v = mp[(size_t)p * (EMB * EMB / 4) + i];
        s.x += v.x; s.y += v.y; s.z += v.z; s.w += v.w;
    }
    __nv_bfloat16 h0, l0, h1, l1, h2, l2, h3, l3;
    split1(s.x, h0, l0); split1(s.y, h1, l1);
    split1(s.z, h2, l2); split1(s.w, h3, l3);
    mth[i] = make_uint2(pack2(h0, h1), pack2(h2, h3));
    mtl[i] = make_uint2(pack2(l0, l1), pack2(l2, l3));
}

// ---------------------------------------------------------------------------
// r1[i] = Wq^T bk, r2[i] = Wk^T bq, c = bq.bk
// ---------------------------------------------------------------------------
__global__ __launch_bounds__(256)
void bias_vec(const __nv_bfloat16* __restrict__ qth, const __nv_bfloat16* __restrict__ qtl,
              const __nv_bfloat16* __restrict__ kth, const __nv_bfloat16* __restrict__ ktl,
              const float* __restrict__ bq, const float* __restrict__ bk,
              float* __restrict__ r1, float* __restrict__ r2, float* __restrict__ cp) {
    const int tid = threadIdx.x;
    if (blockIdx.x == 128) {
        __shared__ float red[8];
        float s = 0.f;
        for (int h = tid; h < EMB; h += 256) s += bq[h] * bk[h];
#pragma unroll
        for (int o = 16; o > 0; o >>= 1) s += __shfl_xor_sync(0xffffffffu, s, o);
        if ((tid & 31) == 0) red[tid >> 5] = s;
        __syncthreads();
        if (tid < 8) {
            s = red[tid];
#pragma unroll
            for (int o = 4; o > 0; o >>= 1) s += __shfl_xor_sync(0xffu, s, o);
            if (tid == 0) cp[0] = s;
        }
        return;
    }
    const int lane = tid & 31;
    const int row = blockIdx.x * 8 + (tid >> 5);
    float s1 = 0.f, s2 = 0.f;
    for (int h = lane; h < EMB; h += 32) {
        const size_t o = (size_t)row * EMB + h;
        s1 += (__bfloat162float(qth[o]) + __bfloat162float(qtl[o])) * bk[h];
        s2 += (__bfloat162float(kth[o]) + __bfloat162float(ktl[o])) * bq[h];
    }
#pragma unroll
    for (int o = 16; o > 0; o >>= 1) {
        s1 += __shfl_xor_sync(0xffffffffu, s1, o);
        s2 += __shfl_xor_sync(0xffffffffu, s2, o);
    }
    if (lane == 0) { r1[row] = s1; r2[row] = s2; }
}

// ---------------------------------------------------------------------------
// u[q] = x[q,:].r1 + c ;  w[q] = x[q,:].r2   (reads raw fp32 x)
// ---------------------------------------------------------------------------
__global__ __launch_bounds__(256)
void gemv_uw(const float* __restrict__ x, const float* __restrict__ r1,
             const float* __restrict__ r2, const float* __restrict__ cp,
             float* __restrict__ u, float* __restrict__ w) {
    const int tid = threadIdx.x;
    const int lane = tid & 31;
    const int q = blockIdx.x * 8 + (tid >> 5);
    float s1 = 0.f, s2 = 0.f;
    const float* xr = x + (size_t)q * EMB;
    for (int i = lane; i < EMB; i += 32) {
        const float xv = xr[i];
        s1 = fmaf(xv, r1[i], s1);
        s2 = fmaf(xv, r2[i], s2);
    }
#pragma unroll
    for (int o = 16; o > 0; o >>= 1) {
        s1 += __shfl_xor_sync(0xffffffffu, s1, o);
        s2 += __shfl_xor_sync(0xffffffffu, s2, o);
    }
    if (lane == 0) { u[q] = s1 + cp[0]; w[q] = s2; }
}

// ---------------------------------------------------------------------------
// Single-pass softmax: e = exp(s) unnormalized bf16 hi/lo; inv[row] = 1/sum.
// ---------------------------------------------------------------------------
__global__ __launch_bounds__(256)
void softmax_pass(const float* __restrict__ S, __nv_bfloat16* __restrict__ ah,
                  __nv_bfloat16* __restrict__ al, float* __restrict__ invp) {
    const int row = blockIdx.x;
    const int q = row & (SEQ - 1);
    const float* p = S + (size_t)row * SEQ;
    const int len = q + 1;
    const int tid = threadIdx.x;
    const size_t base = (size_t)row * SEQ;
    __shared__ float red[32];

    float s = 0.f;
    const int n4 = len >> 2;
    const float4* p4 = (const float4*)p;
    uint2* ah2 = (uint2*)(ah + base);
    uint2* al2 = (uint2*)(al + base);
    for (int i = tid; i < n4; i += 256) {
        const float4 v = p4[i];
        const float e0 = fexp(v.x), e1 = fexp(v.y), e2 = fexp(v.z), e3 = fexp(v.w);
        s += (e0 + e1) + (e2 + e3);
        __nv_bfloat16 h0, l0, h1, l1, h2, l2, h3, l3;
        split1(e0, h0, l0); split1(e1, h1, l1);
        split1(e2, h2, l2); split1(e3, h3, l3);
        ah2[i] = make_uint2(pack2(h0, h1), pack2(h2, h3));
        al2[i] = make_uint2(pack2(l0, l1), pack2(l2, l3));
    }
    for (int k = (n4 << 2) + tid; k < len; k += 256) {
        const float e = fexp(p[k]);
        s += e;
        __nv_bfloat16 h, l;
        split1(e, h, l);
        ah[base + k] = h;
        al[base + k] = l;
    }

#pragma unroll
    for (int o = 16; o > 0; o >>= 1) s += __shfl_xor_sync(0xffffffffu, s, o);
    if ((tid & 31) == 0) red[tid >> 5] = s;
    __syncthreads();
    s = red[tid & 7];
#pragma unroll
    for (int o = 4; o > 0; o >>= 1) s += __shfl_xor_sync(0xffffffffu, s, o);
    if (tid == 0) invp[row] = 1.0f / s;

    const int zend = ((q >> 7) + 1) << 7;
    const __nv_bfloat16 z = __float2bfloat16_rn(0.f);
    for (int k = len + tid; k < zend; k += 256) {
        ah[base + k] = z;
        al[base + k] = z;
    }
}

// ---------------------------------------------------------------------------
extern "C" void kernel_launch(void* const* d_in, const int* in_sizes, int n_in,
                              void* d_out, int out_size) {
    const float* x  = (const float*)d_in[0];
    const float* Wq = (const float*)d_in[1];
    const float* bq = (const float*)d_in[2];
    const float* Wk = (const float*)d_in[3];
    const float* bk = (const float*)d_in[4];
    const float* Wv = (const float*)d_in[5];
    const float* bv = (const float*)d_in[6];
    float* out = (float*)d_out;

    __nv_bfloat16 *xh, *xl, *wvh, *wvl, *qth, *qtl, *kth, *ktl;
    __nv_bfloat16 *mth, *mtl, *th, *tl, *vth, *vtl, *ah, *al;
    float *mp, *s, *inv, *r1, *r2, *c, *u, *w;
    cudaGetSymbolAddress((void**)&xh, g_xh);     cudaGetSymbolAddress((void**)&xl, g_xl);
    cudaGetSymbolAddress((void**)&wvh, g_wvh);   cudaGetSymbolAddress((void**)&wvl, g_wvl);
    cudaGetSymbolAddress((void**)&qth, g_wqth);  cudaGetSymbolAddress((void**)&qtl, g_wqtl);
    cudaGetSymbolAddress((void**)&kth, g_wkth);  cudaGetSymbolAddress((void**)&ktl, g_wktl);
    cudaGetSymbolAddress((void**)&mp, g_mp);
    cudaGetSymbolAddress((void**)&mth, g_mth);   cudaGetSymbolAddress((void**)&mtl, g_mtl);
    cudaGetSymbolAddress((void**)&th, g_th);     cudaGetSymbolAddress((void**)&tl, g_tl);
    cudaGetSymbolAddress((void**)&vth, g_vth);   cudaGetSymbolAddress((void**)&vtl, g_vtl);
    cudaGetSymbolAddress((void**)&ah, g_ah);     cudaGetSymbolAddress((void**)&al, g_al);
    cudaGetSymbolAddress((void**)&s, g_s);       cudaGetSymbolAddress((void**)&inv, g_inv);
    cudaGetSymbolAddress((void**)&r1, g_r1);     cudaGetSymbolAddress((void**)&r2, g_r2);
    cudaGetSymbolAddress((void**)&c, g_c);
    cudaGetSymbolAddress((void**)&u, g_u);       cudaGetSymbolAddress((void**)&w, g_w);

    cudaFuncSetAttribute(gemm_tc<0>, cudaFuncAttributeMaxDynamicSharedMemorySize, GEMM_SMEM);
    cudaFuncSetAttribute(gemm_tc<5>, cudaFuncAttributeMaxDynamicSharedMemorySize, GEMM_SMEM);
    cudaFuncSetAttribute(gemm_tc<6>, cudaFuncAttributeMaxDynamicSharedMemorySize, GEMM_SMEM);
    cudaFuncSetAttribute(gemm_tc<2>, cudaFuncAttributeMaxDynamicSharedMemorySize, GEMM_SMEM);
    cudaFuncSetAttribute(gemm_tc<3>, cudaFuncAttributeMaxDynamicSharedMemorySize, GEMM_SMEM);

    // fork resources (host-side; no device allocation). Destroyed only when
    // not capturing.
    cudaStream_t s2, s3;
    cudaStreamCreate(&s2);
    cudaStreamCreate(&s3);
    cudaEvent_t ev_w, ev_px, ev_red, ev_uw, ev_v;
    cudaEventCreateWithFlags(&ev_w, cudaEventDisableTiming);
    cudaEventCreateWithFlags(&ev_px, cudaEventDisableTiming);
    cudaEventCreateWithFlags(&ev_red, cudaEventDisableTiming);
    cudaEventCreateWithFlags(&ev_uw, cudaEventDisableTiming);
    cudaEventCreateWithFlags(&ev_v, cudaEventDisableTiming);

    // ---- main: weight transposes first (tiny) to unblock Mt + bias
    prep_w<<<2048, 256>>>(Wq, Wk, qth, qtl, kth, ktl);
    cudaEventRecord(ev_w, 0);

    // ---- s3 (tensor-bound): Mt split-K + reduce, overlapping main's prep_x
    cudaStreamWaitEvent(s3, ev_w, 0);
    gemm_tc<6><<<dim3(8, 8, 8), 256, GEMM_SMEM, s3>>>(
        kth, ktl, qth, qtl, nullptr,
        mp, nullptr, nullptr, nullptr, nullptr,
        nullptr, nullptr, nullptr,
        EMB, EMB, EMB, EMB, 0, 0, 0, 1.f);
    reduce_mt<<<EMB * EMB / 4 / 256, 256, 0, s3>>>(
        (const float4*)mp, (uint2*)mth, (uint2*)mtl);
    cudaEventRecord(ev_red, s3);

    // ---- s2 (memory-bound then tensor): bias -> gemv -> V projection
    cudaStreamWaitEvent(s2, ev_w, 0);
    bias_vec<<<129, 256, 0, s2>>>(qth, qtl, kth, ktl, bq, bk, r1, r2, c);
    gemv_uw<<<MTOT / 8, 256, 0, s2>>>(x, r1, r2, c, u, w);
    cudaEventRecord(ev_uw, s2);

    // ---- main (memory-bound): split x + Wv, overlapping s3's Mt
    prep_x<<<(XN4 + WN4) / 256, 256>>>(
        (const float4*)x, (const float4*)Wv,
        (uint2*)xh, (uint2*)xl, (uint2*)wvh, (uint2*)wvl);
    cudaEventRecord(ev_px, 0);

    // ---- s2: V projection (needs xh/wvh from prep_x)
    cudaStreamWaitEvent(s2, ev_px, 0);
    gemm_tc<5><<<dim3(HID / 128, MTOT / 128), 256, GEMM_SMEM, s2>>>(
        xh, xl, wvh, wvl, bv, nullptr, nullptr, nullptr,
        vth, vtl, nullptr, nullptr, nullptr,
        EMB, EMB, EMB, HID, 0, 0, 0, 1.f);
    cudaEventRecord(ev_v, s2);

    // ---- main: t = x·M (needs Mt from s3)
    cudaStreamWaitEvent(0, ev_red, 0);
    gemm_tc<0><<<dim3(EMB / 128, MTOT / 128), 256, GEMM_SMEM>>>(
        xh, xl, mth, mtl, nullptr,
        nullptr, th, tl, nullptr, nullptr,
        nullptr, nullptr, nullptr,
        EMB, EMB, EMB, EMB, 0, 0, 0, 1.f);

    // ---- main: scores (needs u/w from s2)
    cudaStreamWaitEvent(0, ev_uw, 0);
    gemm_tc<2><<<dim3(N_TRI, 1, BATCH), 256, GEMM_SMEM>>>(
        th, tl, xh, xl, nullptr,
        s, nullptr, nullptr, nullptr, nullptr,
        u, w, nullptr,
        EMB, EMB, EMB, SEQ,
        (size_t)SEQ * EMB, (size_t)SEQ * EMB, (size_t)SEQ * SEQ, 0.03125f);

    softmax_pass<<<BATCH * SEQ, 256>>>(s, ah, al, inv);

    // ---- main: AV (needs V from s2)
    cudaStreamWaitEvent(0, ev_v, 0);
    gemm_tc<3><<<dim3(HID / 128, SEQ / 128, BATCH), 256, GEMM_SMEM>>>(
        ah, al, vth, vtl, nullptr,
        out, nullptr, nullptr, nullptr, nullptr,
        nullptr, nullptr, inv,
        SEQ, SEQ, SEQ, HID,
        (size_t)SEQ * SEQ, (size_t)HID * SEQ, (size_t)SEQ * HID, 1.f);

    // cleanup only outside capture
    cudaStreamCaptureStatus cs = cudaStreamCaptureStatusNone;
    cudaStreamIsCapturing(s2, &cs);
    if (cs == cudaStreamCaptureStatusNone) {
        cudaStreamDestroy(s2);
        cudaStreamDestroy(s3);
        cudaEventDestroy(ev_w);
        cudaEventDestroy(ev_px);
        cudaEventDestroy(ev_red);
        cudaEventDestroy(ev_uw);
        cudaEventDestroy(ev_v);
    }
}